// round 11
// baseline (speedup 1.0000x reference)
#include <cuda_runtime.h>
#include <cstdint>

// GumbelSinkhorn: B=128, N=512 rows, M=512 cols, tau=1, 5 iters.
// Register-resident fused pairs. nt-adaptive warp packing:
//   nt>256: warp = 1 row x 512 cols (strip 16 rows)
//   nt>128: warp = 2 rows x 256 cols (strip 32 rows)
//   else  : warp = 4 rows x 128 cols (strip 64 rows)
// ex2 with log2e folded into precomputed reciprocal column scales (g_ics);
// in-kernel colsum inversion via per-batch acq_rel done-counters.

#define BB 128
#define NN 512
#define MM 512
#define LOG2E 1.4426950408889634f

__device__ float    g_E[(size_t)BB * NN * MM];
__device__ float    g_acc[5][BB * MM];
__device__ float    g_ics[5][BB * MM];
__device__ unsigned g_done[5][BB];
__device__ int      g_items[BB * 32];   // (b<<5)|strip
__device__ int      g_cnt;

__device__ __forceinline__ int mode_shift(int nt) {
    return (nt > 256) ? 0 : ((nt > 128) ? 1 : 2);
}
__device__ __forceinline__ float ex2f(float x) {
    float y;
    asm("ex2.approx.f32 %0, %1;" : "=f"(y) : "f"(x));
    return y;
}
__device__ __forceinline__ unsigned atom_inc_acqrel(unsigned* p) {
    unsigned old;
    asm volatile("atom.add.acq_rel.gpu.global.u32 %0, [%1], 1;"
                 : "=r"(old) : "l"(p) : "memory");
    return old;
}
__device__ __forceinline__ float ld_cg(const float* p) {
    float v;
    asm volatile("ld.global.cg.f32 %0, [%1];" : "=f"(v) : "l"(p));
    return v;
}
__device__ __forceinline__ float group_sum(float v, int G) {
    #pragma unroll 1
    for (int d = G >> 1; d; d >>= 1)
        v += __shfl_xor_sync(0xffffffffu, v, d);
    return v;
}

// ---------------------------------------------------------------------------
__global__ void setup_kernel(const int* __restrict__ fa,
                             const int* __restrict__ ta) {
    float4* p = (float4*)&g_acc[0][0];
    int total4 = 5 * BB * MM / 4;
    int gid = blockIdx.x * blockDim.x + threadIdx.x;
    for (int i = gid; i < total4; i += gridDim.x * blockDim.x)
        p[i] = make_float4(0.f, 0.f, 0.f, 0.f);
    if (gid < 5 * BB) (&g_done[0][0])[gid] = 0u;

    if (blockIdx.x == 0 && threadIdx.x < 32) {
        int lane = threadIdx.x;
        int carry = 0;
        for (int g = 0; g < 4; g++) {
            int b = g * 32 + lane;
            int na = fa[b], nt = ta[b];
            int H = 16 << mode_shift(nt);
            int c = (na > 0 && nt > 0) ? (na + H - 1) / H : 0;
            int inc = c;
            #pragma unroll
            for (int d = 1; d < 32; d <<= 1) {
                int t = __shfl_up_sync(0xffffffffu, inc, d);
                if (lane >= d) inc += t;
            }
            int off = carry + inc - c;
            for (int s = 0; s < c; s++) g_items[off + s] = (b << 5) | s;
            carry += __shfl_sync(0xffffffffu, inc, 31);
        }
        if (lane == 0) g_cnt = carry;
    }
}

// ---------------------------------------------------------------------------
// Tail: column partials (flattened, stride-C) + atomic accumulate; the last
// finishing CTA of batch b inverts the 512 column sums into g_ics.
__device__ __forceinline__ void col_tail(float* smf, int stage, float factor,
                                         int b, int na, int nt, int msh, int tid) {
    __syncthreads();
    int C = 512 >> msh;
    int niter = 16 << msh;
    if (tid < C) {
        float s = 0.f;
        #pragma unroll 1
        for (int i = 0; i < niter; i++) s += smf[i * C + tid];
        if (tid < nt) atomicAdd(&g_acc[stage][b * MM + tid], s);
    }
    __syncthreads();
    __shared__ bool last;
    if (tid == 0) {
        int H = 16 << msh;
        unsigned items = (unsigned)((na + H - 1) / H);
        last = (atom_inc_acqrel(&g_done[stage][b]) == items - 1u);
    }
    __syncthreads();
    if (last) {
        float ssum = ld_cg(&g_acc[stage][b * MM + tid]);
        g_ics[stage][b * MM + tid] = (ssum > 0.f) ? __fdividef(factor, ssum) : 0.f;
    }
    __syncthreads();
}

// ---------------------------------------------------------------------------
// Core pair body, shared by init (SRC=logits, scale folds LOG2E directly) and
// pair stages (SRC=g_E, per-column ics). INIT selects the source transform.
template<bool INIT>
__device__ __forceinline__ void pair_body(
        const float* __restrict__ src_base,   // logits (INIT) or g_E
        int stage, float factor,
        const float* __restrict__ ics,        // unused when INIT
        const int* __restrict__ fa, const int* __restrict__ ta,
        float* smf) {
    int cnt = g_cnt;
    int tid = threadIdx.x, w = tid >> 5, lane = tid & 31;
    for (int it = blockIdx.x; it < cnt; it += gridDim.x) {
        int item = g_items[it];
        int b = item >> 5, s = item & 31;
        int na = fa[b], nt = ta[b];
        int msh = mode_shift(nt);
        int G = 32 >> msh, C = 512 >> msh, kst = 128 >> msh;
        int j = lane >> (5 - msh);
        int lsub = lane & (G - 1);
        int gr = s * (16 << msh) + (w << msh) + j;
        bool rowv = (gr < na);
        const float* CS = ics + b * MM;
        const float* Sr = src_base + (size_t)b * NN * MM + (size_t)gr * MM;
        float*       Er = g_E      + (size_t)b * NN * MM + (size_t)gr * MM;

        float4 v[4];
        float racc = 0.f;
        #pragma unroll
        for (int k = 0; k < 4; k++) {
            int cb = lsub * 4 + k * kst;
            v[k] = make_float4(0.f, 0.f, 0.f, 0.f);
            if (rowv && cb < nt) {
                float4 e = *(const float4*)(Sr + cb);
                if (INIT) {
                    v[k].x = ex2f(e.x * LOG2E);
                    v[k].y = (cb + 1 < nt) ? ex2f(e.y * LOG2E) : 0.f;
                    v[k].z = (cb + 2 < nt) ? ex2f(e.z * LOG2E) : 0.f;
                    v[k].w = (cb + 3 < nt) ? ex2f(e.w * LOG2E) : 0.f;
                } else {
                    float4 s4 = *(const float4*)(CS + cb);
                    v[k].x = ex2f(e.x * s4.x);
                    v[k].y = (cb + 1 < nt) ? ex2f(e.y * s4.y) : 0.f;
                    v[k].z = (cb + 2 < nt) ? ex2f(e.z * s4.z) : 0.f;
                    v[k].w = (cb + 3 < nt) ? ex2f(e.w * s4.w) : 0.f;
                }
                racc += (v[k].x + v[k].y) + (v[k].z + v[k].w);
            }
        }
        float rinv = __fdividef(LOG2E, group_sum(racc, G));
        #pragma unroll
        for (int k = 0; k < 4; k++) {
            int cb = lsub * 4 + k * kst;
            float4 o = make_float4(0.f, 0.f, 0.f, 0.f);
            if (rowv && cb < nt) {
                o.x = ex2f(v[k].x * rinv);
                o.y = (cb + 1 < nt) ? ex2f(v[k].y * rinv) : 0.f;
                o.z = (cb + 2 < nt) ? ex2f(v[k].z * rinv) : 0.f;
                o.w = (cb + 3 < nt) ? ex2f(v[k].w * rinv) : 0.f;
                *(float4*)(Er + cb) = o;
            }
            *(float4*)(smf + w * 512 + j * C + cb) = o;
        }
        col_tail(smf, stage, factor, b, na, nt, msh, tid);
    }
}

__global__ void __launch_bounds__(512) init_pair_kernel(
        const float* __restrict__ logits,
        const int* __restrict__ fa, const int* __restrict__ ta) {
    __shared__ float smf[16 * 512];
    pair_body<true>(logits, 0, LOG2E, nullptr, fa, ta, smf);
}

__global__ void __launch_bounds__(512) pair_kernel(
        int p, const int* __restrict__ fa, const int* __restrict__ ta) {
    __shared__ float smf[16 * 512];
    float factor = (p == 3) ? 1.0f : LOG2E;
    pair_body<false>(g_E, p + 1, factor, &g_ics[p][0], fa, ta, smf);
}

// ---------------------------------------------------------------------------
// F: out = E9 * ics[4] in mask, 0 outside. Full [N, M]. grid 4096, warp/row.
__global__ void __launch_bounds__(512) final_kernel(
        float* __restrict__ out,
        const int* __restrict__ fa, const int* __restrict__ ta) {
    int b = blockIdx.x >> 5, r0 = (blockIdx.x & 31) << 4;
    int na = fa[b], nt = ta[b];
    int tid = threadIdx.x, w = tid >> 5, lane = tid & 31;
    const float* Eb = g_E + (size_t)b * NN * MM;
    const float* CS = &g_ics[4][0] + b * MM;
    float*       Ob = out + (size_t)b * NN * MM;
    int gr = r0 + w;
    bool rowv = (gr < na);
    #pragma unroll
    for (int k = 0; k < 4; k++) {
        int cb = lane * 4 + k * 128;
        float4 o = make_float4(0.f, 0.f, 0.f, 0.f);
        if (rowv && cb < nt) {
            float4 s4 = *(const float4*)(CS + cb);
            float4 e  = *(const float4*)(Eb + gr * MM + cb);
            o.x = e.x * s4.x; o.y = e.y * s4.y;
            o.z = e.z * s4.z; o.w = e.w * s4.w;
        }
        *(float4*)(Ob + gr * MM + cb) = o;
    }
}

extern "C" void kernel_launch(void* const* d_in, const int* in_sizes, int n_in,
                              void* d_out, int out_size) {
    const float* logits = (const float*)d_in[0];
    const int*   fa     = (const int*)d_in[1];
    const int*   ta     = (const int*)d_in[2];
    float*       out    = (float*)d_out;

    setup_kernel<<<256, 256>>>(fa, ta);
    init_pair_kernel<<<2048, 512>>>(logits, fa, ta);
    for (int p = 0; p < 4; p++)
        pair_kernel<<<2048, 512>>>(p, fa, ta);
    final_kernel<<<4096, 512>>>(out, fa, ta);
}